// round 3
// baseline (speedup 1.0000x reference)
#include <cuda_runtime.h>
#include <cstdint>

// DeltaModulationEncoder, round 2: chain-minimized formulation.
// Per step (bit-exact vs reference):
//   rp = recon + th ; rm = recon - th    (off critical path, parallel w/ d)
//   d  = x - recon                        (FADD, +4)
//   gp = d > th ; gm = d < -th            (FSETP, +4, consumed as data)
//   recon' = gm ? rm : (gp ? rp : recon)  (2x FSEL, +8)   => 16 cyc chain/step
//   net    = gp ? 1 : (gm ? -1 : 0)       (off chain)
//
// Lane = row (4096 rows), 128 blocks x 32 threads. Each lane streams its own
// contiguous 32KB row; one 128B line (8 x float4) prefetch buffer, outputs
// stored immediately per float4 to keep register count low (no spills).

#define TT 8192
#define NITER (TT / 32)   // 256 iterations of 32 timesteps (one 128B line)

__global__ void __launch_bounds__(32, 1)
delta_mod_kernel(const float* __restrict__ x, float* __restrict__ out, int rows)
{
    const int row = blockIdx.x * 32 + threadIdx.x;
    if (row >= rows) return;

    const float4* __restrict__ px = reinterpret_cast<const float4*>(x + (size_t)row * TT);
    float4* __restrict__ po       = reinterpret_cast<float4*>(out + (size_t)row * TT);

    const float TH  = 0.1f;   // bits 0x3DCCCCCD, == jnp.float32(0.1)
    const float NTH = -0.1f;

    float recon = 0.0f;

    // prefetch one full 128B line (8 x float4)
    float4 buf[8];
#pragma unroll
    for (int j = 0; j < 8; ++j) buf[j] = px[j];

    for (int it = 0; it < NITER; ++it) {
        const int nxt = (it + 1 < NITER) ? (it + 1) : (NITER - 1);

#pragma unroll
        for (int j = 0; j < 8; ++j) {
            float4 c = buf[j];
            buf[j] = px[nxt * 8 + j];   // prefetch next line's chunk early

            float4 o;

            {
                float rp = recon + TH;
                float rm = recon + NTH;
                float d  = c.x - recon;
                bool gp = d > TH;
                bool gm = d < NTH;
                float r1 = gp ? rp : recon;
                recon = gm ? rm : r1;
                o.x = gp ? 1.0f : (gm ? -1.0f : 0.0f);
            }
            {
                float rp = recon + TH;
                float rm = recon + NTH;
                float d  = c.y - recon;
                bool gp = d > TH;
                bool gm = d < NTH;
                float r1 = gp ? rp : recon;
                recon = gm ? rm : r1;
                o.y = gp ? 1.0f : (gm ? -1.0f : 0.0f);
            }
            {
                float rp = recon + TH;
                float rm = recon + NTH;
                float d  = c.z - recon;
                bool gp = d > TH;
                bool gm = d < NTH;
                float r1 = gp ? rp : recon;
                recon = gm ? rm : r1;
                o.z = gp ? 1.0f : (gm ? -1.0f : 0.0f);
            }
            {
                float rp = recon + TH;
                float rm = recon + NTH;
                float d  = c.w - recon;
                bool gp = d > TH;
                bool gm = d < NTH;
                float r1 = gp ? rp : recon;
                recon = gm ? rm : r1;
                o.w = gp ? 1.0f : (gm ? -1.0f : 0.0f);
            }

            po[it * 8 + j] = o;   // store immediately, off chain
        }
    }
}

extern "C" void kernel_launch(void* const* d_in, const int* in_sizes, int n_in,
                              void* d_out, int out_size)
{
    const float* x = (const float*)d_in[0];
    float* out = (float*)d_out;

    const int rows = in_sizes[0] / TT;      // 4096
    const int blocks = (rows + 31) / 32;    // 128

    delta_mod_kernel<<<blocks, 32>>>(x, out, rows);
}

// round 6
// speedup vs baseline: 1.2605x; 1.2605x over previous
#include <cuda_runtime.h>
#include <cstdint>

// DeltaModulationEncoder, round 3/4/5: predicate-free recurrence via FSET.
//   d     = x - recon                      (FADD, 4)
//   p     = set.gt.f32(d,  th) -> 1.0/0.0  (FSET, 4)
//   m     = set.lt.f32(d, -th) -> 1.0/0.0  (FSET, 4, parallel with p)
//   net   = p - m                          (FADD, 4)  == output spike
//   recon = fma(net, th, recon)            (FFMA, 4)  exact: net*th in {-0.1f,0,0.1f}
// Chain = 16 cyc/step, no predicates anywhere on the recurrence.
//
// Lane = row (4096 rows), 128 blocks x 32 threads, each lane streams its
// contiguous 32KB row; one 128B line (8 x float4) prefetched a full line
// (32 steps ~ 512 cyc) ahead to cover DRAM latency.

#define TT 8192
#define NITER (TT / 32)   // 256

__device__ __forceinline__ float fset_gt(float a, float b) {
    float r;
    asm("set.gt.f32.f32 %0, %1, %2;" : "=f"(r) : "f"(a), "f"(b));
    return r;
}
__device__ __forceinline__ float fset_lt(float a, float b) {
    float r;
    asm("set.lt.f32.f32 %0, %1, %2;" : "=f"(r) : "f"(a), "f"(b));
    return r;
}

__global__ void __launch_bounds__(32, 1)
delta_mod_kernel(const float* __restrict__ x, float* __restrict__ out, int rows)
{
    const int row = blockIdx.x * 32 + threadIdx.x;
    if (row >= rows) return;

    const float4* __restrict__ px = reinterpret_cast<const float4*>(x + (size_t)row * TT);
    float4* __restrict__ po       = reinterpret_cast<float4*>(out + (size_t)row * TT);

    const float TH  = 0.1f;    // bits 0x3DCCCCCD == jnp.float32(0.1)
    const float NTH = -0.1f;

    float recon = 0.0f;

    // prefetch one full 128B line (8 x float4)
    float4 buf[8];
#pragma unroll
    for (int j = 0; j < 8; ++j) buf[j] = px[j];

    for (int it = 0; it < NITER; ++it) {
        const int nxt = (it + 1 < NITER) ? (it + 1) : (NITER - 1);

#pragma unroll
        for (int j = 0; j < 8; ++j) {
            float4 c = buf[j];
            buf[j] = px[nxt * 8 + j];   // prefetch next line's chunk early

            float4 o;

            {
                float d   = c.x - recon;
                float p   = fset_gt(d, TH);
                float m   = fset_lt(d, NTH);
                float net = p - m;
                recon     = fmaf(net, TH, recon);
                o.x = net;
            }
            {
                float d   = c.y - recon;
                float p   = fset_gt(d, TH);
                float m   = fset_lt(d, NTH);
                float net = p - m;
                recon     = fmaf(net, TH, recon);
                o.y = net;
            }
            {
                float d   = c.z - recon;
                float p   = fset_gt(d, TH);
                float m   = fset_lt(d, NTH);
                float net = p - m;
                recon     = fmaf(net, TH, recon);
                o.z = net;
            }
            {
                float d   = c.w - recon;
                float p   = fset_gt(d, TH);
                float m   = fset_lt(d, NTH);
                float net = p - m;
                recon     = fmaf(net, TH, recon);
                o.w = net;
            }

            po[it * 8 + j] = o;   // off-chain store
        }
    }
}

extern "C" void kernel_launch(void* const* d_in, const int* in_sizes, int n_in,
                              void* d_out, int out_size)
{
    const float* x = (const float*)d_in[0];
    float* out = (float*)d_out;

    const int rows = in_sizes[0] / TT;      // 4096
    const int blocks = (rows + 31) / 32;    // 128

    delta_mod_kernel<<<blocks, 32>>>(x, out, rows);
}